// round 1
// baseline (speedup 1.0000x reference)
#include <cuda_runtime.h>
#include <stdint.h>

#define NN 100000
#define NE 3200000
#define DH 8
#define DLAT 11

// ---------------- scratch (static device globals; no allocation) ----------------
// rec layout per node (32 floats): [a+be1 (8) | q (8) | b (8) | p (8)]
//   col side of an edge needs a (compute) and q (scatter to s2[row])  -> floats 0..15
//   row side needs b (compute) and p (scatter to s1[col])             -> floats 16..31
__device__ float g_rec[NN * 32];
__device__ float g_h[NN * 12];     // [H(8), x(3), pad]
__device__ float g_s1[NN * 8];     // sum over in-edges of e*p[row]   (mi @ Wn1[0:11])
__device__ float g_s2[NN * 8];     // sum over out-edges of e*q[col]  (mo @ Wn1[11:22])
__device__ int   g_idx[2 * NE];    // normalized int32 indices: [row(E), col(E)]
__device__ int   g_is64;

// ---------------- math helpers ----------------
__device__ __forceinline__ float ftanh(float x) {
    x = fminf(fmaxf(x, -15.f), 15.f);
    float t = __expf(2.f * x);
    return __fdividef(t - 1.f, t + 1.f);
}
__device__ __forceinline__ float fsig(float x) {
    x = fminf(fmaxf(x, -30.f), 30.f);
    return __fdividef(1.f, 1.f + __expf(-x));
}
__device__ __forceinline__ void red_add_v4(float* p, float4 v) {
    asm volatile("red.global.add.v4.f32 [%0], {%1,%2,%3,%4};"
                 :: "l"(p), "f"(v.x), "f"(v.y), "f"(v.z), "f"(v.w) : "memory");
}

// ---------------- index dtype detect + normalize ----------------
__global__ void k_detect(const unsigned* raw) {
    int ok = 1;
#pragma unroll
    for (int i = 0; i < 32; i++)
        if (raw[2 * i + 1] != 0u) ok = 0;   // int64 little-endian: high words are 0
    g_is64 = ok;
}

__global__ void k_convert(const void* raw) {
    int i = blockIdx.x * blockDim.x + threadIdx.x;
    if (i >= 2 * NE) return;
    if (g_is64) g_idx[i] = (int)((const long long*)raw)[i];
    else        g_idx[i] = ((const int*)raw)[i];
}

// ---------------- per-node record builder ----------------
// h[11] in regs; sWe1: We1 (22x8), sbe1: be1 (8), sWn1: Wn1 rows 0..21 (22x8)
__device__ __forceinline__ void write_rec_and_clear(
    int v, const float* h, const float* sWe1, const float* sbe1, const float* sWn1)
{
    float a[8], b[8], p[8], q[8];
#pragma unroll
    for (int k = 0; k < 8; k++) { a[k] = sbe1[k]; b[k] = 0.f; p[k] = 0.f; q[k] = 0.f; }
#pragma unroll
    for (int i = 0; i < 11; i++) {
        float hv = h[i];
#pragma unroll
        for (int k = 0; k < 8; k++) {
            a[k] = fmaf(hv, sWe1[i * 8 + k],        a[k]);
            b[k] = fmaf(hv, sWe1[(11 + i) * 8 + k], b[k]);
            p[k] = fmaf(hv, sWn1[i * 8 + k],        p[k]);
            q[k] = fmaf(hv, sWn1[(11 + i) * 8 + k], q[k]);
        }
    }
    float4* r = (float4*)(g_rec + (size_t)v * 32);
    r[0] = make_float4(a[0], a[1], a[2], a[3]);
    r[1] = make_float4(a[4], a[5], a[6], a[7]);
    r[2] = make_float4(q[0], q[1], q[2], q[3]);
    r[3] = make_float4(q[4], q[5], q[6], q[7]);
    r[4] = make_float4(b[0], b[1], b[2], b[3]);
    r[5] = make_float4(b[4], b[5], b[6], b[7]);
    r[6] = make_float4(p[0], p[1], p[2], p[3]);
    r[7] = make_float4(p[4], p[5], p[6], p[7]);
    float4 z = make_float4(0.f, 0.f, 0.f, 0.f);
    float4* s1 = (float4*)(g_s1 + (size_t)v * 8);
    float4* s2 = (float4*)(g_s2 + (size_t)v * 8);
    s1[0] = z; s1[1] = z; s2[0] = z; s2[1] = z;
}

// ---------------- init: H = tanh(x@W_in + b_in); h = [H, x]; build rec; clear s ----------------
__global__ void k_init(const float* __restrict__ x,
                       const float* __restrict__ W_in, const float* __restrict__ b_in,
                       const float* __restrict__ We1,  const float* __restrict__ be1,
                       const float* __restrict__ Wn1)
{
    __shared__ float sWin[24], sbin[8], sWe1[176], sbe1[8], sWn1[176];
    int tid = threadIdx.x;
    if (tid < 24) sWin[tid] = W_in[tid];
    if (tid < 8)  sbin[tid] = b_in[tid];
    if (tid < 8)  sbe1[tid] = be1[tid];
    for (int i = tid; i < 176; i += blockDim.x) sWe1[i] = We1[i];
    for (int i = tid; i < 176; i += blockDim.x) sWn1[i] = Wn1[i];
    __syncthreads();

    int v = blockIdx.x * blockDim.x + tid;
    if (v >= NN) return;

    float xv0 = x[v * 3 + 0], xv1 = x[v * 3 + 1], xv2 = x[v * 3 + 2];
    float h[11];
#pragma unroll
    for (int k = 0; k < 8; k++) {
        float s = sbin[k];
        s = fmaf(xv0, sWin[0 * 8 + k], s);
        s = fmaf(xv1, sWin[1 * 8 + k], s);
        s = fmaf(xv2, sWin[2 * 8 + k], s);
        h[k] = ftanh(s);
    }
    h[8] = xv0; h[9] = xv1; h[10] = xv2;

    float4* hp = (float4*)(g_h + (size_t)v * 12);
    hp[0] = make_float4(h[0], h[1], h[2],  h[3]);
    hp[1] = make_float4(h[4], h[5], h[6],  h[7]);
    hp[2] = make_float4(h[8], h[9], h[10], 0.f);

    write_rec_and_clear(v, h, sWe1, sbe1, sWn1);
}

// ---------------- edge pass: compute e, scatter projected messages ----------------
__global__ void k_edge(const float* __restrict__ We2, const float* __restrict__ be2)
{
    int j = blockIdx.x * blockDim.x + threadIdx.x;
    if (j >= NE) return;
    int row = g_idx[j];
    int col = g_idx[NE + j];

    const float4* rc = (const float4*)(g_rec + (size_t)col * 32);      // a, q
    const float4* rr = (const float4*)(g_rec + (size_t)row * 32 + 16); // b, p
    float4 a0 = rc[0], a1 = rc[1], q0 = rc[2], q1 = rc[3];
    float4 b0 = rr[0], b1 = rr[1], p0 = rr[2], p1 = rr[3];

    float z = __ldg(be2);
    z = fmaf(__ldg(We2 + 0), ftanh(a0.x + b0.x), z);
    z = fmaf(__ldg(We2 + 1), ftanh(a0.y + b0.y), z);
    z = fmaf(__ldg(We2 + 2), ftanh(a0.z + b0.z), z);
    z = fmaf(__ldg(We2 + 3), ftanh(a0.w + b0.w), z);
    z = fmaf(__ldg(We2 + 4), ftanh(a1.x + b1.x), z);
    z = fmaf(__ldg(We2 + 5), ftanh(a1.y + b1.y), z);
    z = fmaf(__ldg(We2 + 6), ftanh(a1.z + b1.z), z);
    z = fmaf(__ldg(We2 + 7), ftanh(a1.w + b1.w), z);
    float e = fsig(z);

    // s1[col] += e * p[row]   (feeds mi @ Wn1[0:11])
    red_add_v4(g_s1 + (size_t)col * 8,     make_float4(e * p0.x, e * p0.y, e * p0.z, e * p0.w));
    red_add_v4(g_s1 + (size_t)col * 8 + 4, make_float4(e * p1.x, e * p1.y, e * p1.z, e * p1.w));
    // s2[row] += e * q[col]   (feeds mo @ Wn1[11:22])
    red_add_v4(g_s2 + (size_t)row * 8,     make_float4(e * q0.x, e * q0.y, e * q0.z, e * q0.w));
    red_add_v4(g_s2 + (size_t)row * 8 + 4, make_float4(e * q1.x, e * q1.y, e * q1.z, e * q1.w));
}

// ---------------- node pass: node MLP, rebuild h + rec, clear s ----------------
__global__ void k_node(const float* __restrict__ We1, const float* __restrict__ be1,
                       const float* __restrict__ Wn1, const float* __restrict__ bn1,
                       const float* __restrict__ Wn2, const float* __restrict__ bn2)
{
    __shared__ float sWe1[176], sbe1[8], sWn1[264], sbn1[8], sWn2[64], sbn2[8];
    int tid = threadIdx.x;
    for (int i = tid; i < 176; i += blockDim.x) sWe1[i] = We1[i];
    for (int i = tid; i < 264; i += blockDim.x) sWn1[i] = Wn1[i];
    for (int i = tid; i < 64;  i += blockDim.x) sWn2[i] = Wn2[i];
    if (tid < 8) { sbe1[tid] = be1[tid]; sbn1[tid] = bn1[tid]; sbn2[tid] = bn2[tid]; }
    __syncthreads();

    int v = blockIdx.x * blockDim.x + tid;
    if (v >= NN) return;

    const float4* hp = (const float4*)(g_h + (size_t)v * 12);
    float4 h0 = hp[0], h1 = hp[1], h2 = hp[2];
    float h[11] = {h0.x, h0.y, h0.z, h0.w, h1.x, h1.y, h1.z, h1.w, h2.x, h2.y, h2.z};

    const float4* s1p = (const float4*)(g_s1 + (size_t)v * 8);
    const float4* s2p = (const float4*)(g_s2 + (size_t)v * 8);
    float4 sa0 = s1p[0], sa1 = s1p[1], sb0 = s2p[0], sb1 = s2p[1];
    float pre[8] = {sa0.x + sb0.x, sa0.y + sb0.y, sa0.z + sb0.z, sa0.w + sb0.w,
                    sa1.x + sb1.x, sa1.y + sb1.y, sa1.z + sb1.z, sa1.w + sb1.w};

#pragma unroll
    for (int k = 0; k < 8; k++) {
        float s = pre[k] + sbn1[k];
#pragma unroll
        for (int i = 0; i < 11; i++)
            s = fmaf(h[i], sWn1[(22 + i) * 8 + k], s);   // M = [mi, mo, h]; h uses rows 22..32
        pre[k] = ftanh(s);
    }
    float hn[11];
#pragma unroll
    for (int k = 0; k < 8; k++) {
        float s = sbn2[k];
#pragma unroll
        for (int j = 0; j < 8; j++)
            s = fmaf(pre[j], sWn2[j * 8 + k], s);
        hn[k] = ftanh(s);
    }
    hn[8] = h[8]; hn[9] = h[9]; hn[10] = h[10];   // x is carried along

    float4* hw = (float4*)(g_h + (size_t)v * 12);
    hw[0] = make_float4(hn[0], hn[1], hn[2],  hn[3]);
    hw[1] = make_float4(hn[4], hn[5], hn[6],  hn[7]);
    hw[2] = make_float4(hn[8], hn[9], hn[10], 0.f);

    write_rec_and_clear(v, hn, sWe1, sbe1, sWn1);
}

// ---------------- final edge pass: write e to output ----------------
__global__ void k_out(const float* __restrict__ We2, const float* __restrict__ be2,
                      float* __restrict__ out)
{
    int j = blockIdx.x * blockDim.x + threadIdx.x;
    if (j >= NE) return;
    int row = g_idx[j];
    int col = g_idx[NE + j];

    const float4* rc = (const float4*)(g_rec + (size_t)col * 32);      // a
    const float4* rr = (const float4*)(g_rec + (size_t)row * 32 + 16); // b
    float4 a0 = rc[0], a1 = rc[1];
    float4 b0 = rr[0], b1 = rr[1];

    float z = __ldg(be2);
    z = fmaf(__ldg(We2 + 0), ftanh(a0.x + b0.x), z);
    z = fmaf(__ldg(We2 + 1), ftanh(a0.y + b0.y), z);
    z = fmaf(__ldg(We2 + 2), ftanh(a0.z + b0.z), z);
    z = fmaf(__ldg(We2 + 3), ftanh(a0.w + b0.w), z);
    z = fmaf(__ldg(We2 + 4), ftanh(a1.x + b1.x), z);
    z = fmaf(__ldg(We2 + 5), ftanh(a1.y + b1.y), z);
    z = fmaf(__ldg(We2 + 6), ftanh(a1.z + b1.z), z);
    z = fmaf(__ldg(We2 + 7), ftanh(a1.w + b1.w), z);
    out[j] = fsig(z);
}

// ---------------- launch ----------------
extern "C" void kernel_launch(void* const* d_in, const int* in_sizes, int n_in,
                              void* d_out, int out_size)
{
    const float* x    = (const float*)d_in[0];
    const void*  eidx = d_in[1];
    const float* W_in = (const float*)d_in[2];
    const float* b_in = (const float*)d_in[3];
    const float* We1  = (const float*)d_in[4];
    const float* be1  = (const float*)d_in[5];
    const float* We2  = (const float*)d_in[6];
    const float* be2  = (const float*)d_in[7];
    const float* Wn1  = (const float*)d_in[8];
    const float* bn1  = (const float*)d_in[9];
    const float* Wn2  = (const float*)d_in[10];
    const float* bn2  = (const float*)d_in[11];
    float* out = (float*)d_out;

    const int TB = 256;
    const int nodeBlocks = (NN + TB - 1) / TB;
    const int edgeBlocks = (NE + TB - 1) / TB;
    const int cvtBlocks  = (2 * NE + TB - 1) / TB;

    k_detect<<<1, 1>>>((const unsigned*)eidx);
    k_convert<<<cvtBlocks, TB>>>(eidx);
    k_init<<<nodeBlocks, TB>>>(x, W_in, b_in, We1, be1, Wn1);
    for (int it = 0; it < 3; it++) {
        k_edge<<<edgeBlocks, TB>>>(We2, be2);
        k_node<<<nodeBlocks, TB>>>(We1, be1, Wn1, bn1, Wn2, bn2);
    }
    k_out<<<edgeBlocks, TB>>>(We2, be2, out);
}

// round 2
// speedup vs baseline: 1.4135x; 1.4135x over previous
#include <cuda_runtime.h>
#include <cuda_fp16.h>
#include <stdint.h>

#define NN 100000
#define NE 3200000

// ---------------- scratch (static device globals; no allocation) ----------------
// rec layout per node: 32 halves (64B): [a+be1 (8h) | q (8h) | b (8h) | p (8h)]
//   col side of an edge: a (compute) + q (scatter to s2[row])  -> halves 0..15  (2x LDG.128)
//   row side of an edge: b (compute) + p (scatter to s1[col])  -> halves 16..31 (2x LDG.128)
__device__ __align__(16) __half g_rec[NN * 32];
__device__ __align__(16) float  g_h[NN * 12];    // [H(8), x(3), pad] fp32
__device__ __align__(16) float  g_s1[NN * 8];    // sum_in  e*p[row]  (mi @ Wn1[0:11])
__device__ __align__(16) float  g_s2[NN * 8];    // sum_out e*q[col]  (mo @ Wn1[11:22])
__device__ int   g_idx[2 * NE];                  // normalized int32: [row(E), col(E)]
__device__ int   g_is64;

// ---------------- math helpers ----------------
__device__ __forceinline__ float ftanh(float x) {
    x = fminf(fmaxf(x, -15.f), 15.f);
    float t = __expf(2.f * x);
    return __fdividef(t - 1.f, t + 1.f);
}
__device__ __forceinline__ float fsig(float x) {
    x = fminf(fmaxf(x, -30.f), 30.f);
    return __fdividef(1.f, 1.f + __expf(-x));
}
__device__ __forceinline__ void red_add_v4(float* p, float4 v) {
    asm volatile("red.global.add.v4.f32 [%0], {%1,%2,%3,%4};"
                 :: "l"(p), "f"(v.x), "f"(v.y), "f"(v.z), "f"(v.w) : "memory");
}

// ---------------- index dtype detect + normalize ----------------
__global__ void k_detect(const unsigned* raw) {
    int ok = 1;
#pragma unroll
    for (int i = 0; i < 32; i++)
        if (raw[2 * i + 1] != 0u) ok = 0;   // int64 LE: high words all zero
    g_is64 = ok;
}

__global__ void k_convert(const void* raw) {
    int i = blockIdx.x * blockDim.x + threadIdx.x;
    if (i >= 2 * NE) return;
    if (g_is64) g_idx[i] = (int)((const long long*)raw)[i];
    else        g_idx[i] = ((const int*)raw)[i];
}

// ---------------- per-node record builder (fp32 compute -> fp16 store) ----------------
__device__ __forceinline__ void write_rec_and_clear(
    int v, const float* h, const float* sWe1, const float* sbe1, const float* sWn1)
{
    float a[8], b[8], p[8], q[8];
#pragma unroll
    for (int k = 0; k < 8; k++) { a[k] = sbe1[k]; b[k] = 0.f; p[k] = 0.f; q[k] = 0.f; }
#pragma unroll
    for (int i = 0; i < 11; i++) {
        float hv = h[i];
#pragma unroll
        for (int k = 0; k < 8; k++) {
            a[k] = fmaf(hv, sWe1[i * 8 + k],        a[k]);
            b[k] = fmaf(hv, sWe1[(11 + i) * 8 + k], b[k]);
            p[k] = fmaf(hv, sWn1[i * 8 + k],        p[k]);
            q[k] = fmaf(hv, sWn1[(11 + i) * 8 + k], q[k]);
        }
    }
    __half2* r = (__half2*)(g_rec + v * 32);
    r[0]  = __float22half2_rn(make_float2(a[0], a[1]));
    r[1]  = __float22half2_rn(make_float2(a[2], a[3]));
    r[2]  = __float22half2_rn(make_float2(a[4], a[5]));
    r[3]  = __float22half2_rn(make_float2(a[6], a[7]));
    r[4]  = __float22half2_rn(make_float2(q[0], q[1]));
    r[5]  = __float22half2_rn(make_float2(q[2], q[3]));
    r[6]  = __float22half2_rn(make_float2(q[4], q[5]));
    r[7]  = __float22half2_rn(make_float2(q[6], q[7]));
    r[8]  = __float22half2_rn(make_float2(b[0], b[1]));
    r[9]  = __float22half2_rn(make_float2(b[2], b[3]));
    r[10] = __float22half2_rn(make_float2(b[4], b[5]));
    r[11] = __float22half2_rn(make_float2(b[6], b[7]));
    r[12] = __float22half2_rn(make_float2(p[0], p[1]));
    r[13] = __float22half2_rn(make_float2(p[2], p[3]));
    r[14] = __float22half2_rn(make_float2(p[4], p[5]));
    r[15] = __float22half2_rn(make_float2(p[6], p[7]));

    float4 z = make_float4(0.f, 0.f, 0.f, 0.f);
    float4* s1 = (float4*)(g_s1 + v * 8);
    float4* s2 = (float4*)(g_s2 + v * 8);
    s1[0] = z; s1[1] = z; s2[0] = z; s2[1] = z;
}

// ---------------- init ----------------
__global__ void k_init(const float* __restrict__ x,
                       const float* __restrict__ W_in, const float* __restrict__ b_in,
                       const float* __restrict__ We1,  const float* __restrict__ be1,
                       const float* __restrict__ Wn1)
{
    __shared__ float sWin[24], sbin[8], sWe1[176], sbe1[8], sWn1[176];
    int tid = threadIdx.x;
    if (tid < 24) sWin[tid] = W_in[tid];
    if (tid < 8)  sbin[tid] = b_in[tid];
    if (tid < 8)  sbe1[tid] = be1[tid];
    for (int i = tid; i < 176; i += blockDim.x) sWe1[i] = We1[i];
    for (int i = tid; i < 176; i += blockDim.x) sWn1[i] = Wn1[i];
    __syncthreads();

    int v = blockIdx.x * blockDim.x + tid;
    if (v >= NN) return;

    float xv0 = x[v * 3 + 0], xv1 = x[v * 3 + 1], xv2 = x[v * 3 + 2];
    float h[11];
#pragma unroll
    for (int k = 0; k < 8; k++) {
        float s = sbin[k];
        s = fmaf(xv0, sWin[0 * 8 + k], s);
        s = fmaf(xv1, sWin[1 * 8 + k], s);
        s = fmaf(xv2, sWin[2 * 8 + k], s);
        h[k] = ftanh(s);
    }
    h[8] = xv0; h[9] = xv1; h[10] = xv2;

    float4* hp = (float4*)(g_h + v * 12);
    hp[0] = make_float4(h[0], h[1], h[2],  h[3]);
    hp[1] = make_float4(h[4], h[5], h[6],  h[7]);
    hp[2] = make_float4(h[8], h[9], h[10], 0.f);

    write_rec_and_clear(v, h, sWe1, sbe1, sWn1);
}

// ---------------- edge pass: gather fp16 rec, compute e, scatter fp32 ----------------
__global__ void k_edge(const float* __restrict__ We2, const float* __restrict__ be2)
{
    int j = blockIdx.x * blockDim.x + threadIdx.x;
    if (j >= NE) return;
    int row = g_idx[j];
    int col = g_idx[NE + j];

    const uint4* rc = (const uint4*)(g_rec + col * 32);       // a | q
    const uint4* rr = (const uint4*)(g_rec + row * 32 + 16);  // b | p
    uint4 aU = rc[0], qU = rc[1];
    uint4 bU = rr[0], pU = rr[1];

    const __half2* ah = (const __half2*)&aU;
    const __half2* bh = (const __half2*)&bU;
    const __half2* qh = (const __half2*)&qU;
    const __half2* ph = (const __half2*)&pU;

    float z = __ldg(be2);
#pragma unroll
    for (int k = 0; k < 4; k++) {
        float2 t = __half22float2(__hadd2(ah[k], bh[k]));
        z = fmaf(__ldg(We2 + 2 * k),     ftanh(t.x), z);
        z = fmaf(__ldg(We2 + 2 * k + 1), ftanh(t.y), z);
    }
    float e = fsig(z);

    float2 p0 = __half22float2(ph[0]), p1 = __half22float2(ph[1]);
    float2 p2 = __half22float2(ph[2]), p3 = __half22float2(ph[3]);
    float2 q0 = __half22float2(qh[0]), q1 = __half22float2(qh[1]);
    float2 q2 = __half22float2(qh[2]), q3 = __half22float2(qh[3]);

    // s1[col] += e * p[row]
    red_add_v4(g_s1 + col * 8,     make_float4(e * p0.x, e * p0.y, e * p1.x, e * p1.y));
    red_add_v4(g_s1 + col * 8 + 4, make_float4(e * p2.x, e * p2.y, e * p3.x, e * p3.y));
    // s2[row] += e * q[col]
    red_add_v4(g_s2 + row * 8,     make_float4(e * q0.x, e * q0.y, e * q1.x, e * q1.y));
    red_add_v4(g_s2 + row * 8 + 4, make_float4(e * q2.x, e * q2.y, e * q3.x, e * q3.y));
}

// ---------------- node pass ----------------
__global__ void k_node(const float* __restrict__ We1, const float* __restrict__ be1,
                       const float* __restrict__ Wn1, const float* __restrict__ bn1,
                       const float* __restrict__ Wn2, const float* __restrict__ bn2)
{
    __shared__ float sWe1[176], sbe1[8], sWn1[264], sbn1[8], sWn2[64], sbn2[8];
    int tid = threadIdx.x;
    for (int i = tid; i < 176; i += blockDim.x) sWe1[i] = We1[i];
    for (int i = tid; i < 264; i += blockDim.x) sWn1[i] = Wn1[i];
    for (int i = tid; i < 64;  i += blockDim.x) sWn2[i] = Wn2[i];
    if (tid < 8) { sbe1[tid] = be1[tid]; sbn1[tid] = bn1[tid]; sbn2[tid] = bn2[tid]; }
    __syncthreads();

    int v = blockIdx.x * blockDim.x + tid;
    if (v >= NN) return;

    const float4* hp = (const float4*)(g_h + v * 12);
    float4 h0 = hp[0], h1 = hp[1], h2 = hp[2];
    float h[11] = {h0.x, h0.y, h0.z, h0.w, h1.x, h1.y, h1.z, h1.w, h2.x, h2.y, h2.z};

    const float4* s1p = (const float4*)(g_s1 + v * 8);
    const float4* s2p = (const float4*)(g_s2 + v * 8);
    float4 sa0 = s1p[0], sa1 = s1p[1], sb0 = s2p[0], sb1 = s2p[1];
    float pre[8] = {sa0.x + sb0.x, sa0.y + sb0.y, sa0.z + sb0.z, sa0.w + sb0.w,
                    sa1.x + sb1.x, sa1.y + sb1.y, sa1.z + sb1.z, sa1.w + sb1.w};

#pragma unroll
    for (int k = 0; k < 8; k++) {
        float s = pre[k] + sbn1[k];
#pragma unroll
        for (int i = 0; i < 11; i++)
            s = fmaf(h[i], sWn1[(22 + i) * 8 + k], s);   // M = [mi, mo, h]
        pre[k] = ftanh(s);
    }
    float hn[11];
#pragma unroll
    for (int k = 0; k < 8; k++) {
        float s = sbn2[k];
#pragma unroll
        for (int jj = 0; jj < 8; jj++)
            s = fmaf(pre[jj], sWn2[jj * 8 + k], s);
        hn[k] = ftanh(s);
    }
    hn[8] = h[8]; hn[9] = h[9]; hn[10] = h[10];

    float4* hw = (float4*)(g_h + v * 12);
    hw[0] = make_float4(hn[0], hn[1], hn[2],  hn[3]);
    hw[1] = make_float4(hn[4], hn[5], hn[6],  hn[7]);
    hw[2] = make_float4(hn[8], hn[9], hn[10], 0.f);

    write_rec_and_clear(v, hn, sWe1, sbe1, sWn1);
}

// ---------------- final edge pass: only a,b needed (2 gathers, no scatter) ----------------
__global__ void k_out(const float* __restrict__ We2, const float* __restrict__ be2,
                      float* __restrict__ out)
{
    int j = blockIdx.x * blockDim.x + threadIdx.x;
    if (j >= NE) return;
    int row = g_idx[j];
    int col = g_idx[NE + j];

    uint4 aU = *(const uint4*)(g_rec + col * 32);       // a
    uint4 bU = *(const uint4*)(g_rec + row * 32 + 16);  // b
    const __half2* ah = (const __half2*)&aU;
    const __half2* bh = (const __half2*)&bU;

    float z = __ldg(be2);
#pragma unroll
    for (int k = 0; k < 4; k++) {
        float2 t = __half22float2(__hadd2(ah[k], bh[k]));
        z = fmaf(__ldg(We2 + 2 * k),     ftanh(t.x), z);
        z = fmaf(__ldg(We2 + 2 * k + 1), ftanh(t.y), z);
    }
    out[j] = fsig(z);
}

// ---------------- launch ----------------
extern "C" void kernel_launch(void* const* d_in, const int* in_sizes, int n_in,
                              void* d_out, int out_size)
{
    const float* x    = (const float*)d_in[0];
    const void*  eidx = d_in[1];
    const float* W_in = (const float*)d_in[2];
    const float* b_in = (const float*)d_in[3];
    const float* We1  = (const float*)d_in[4];
    const float* be1  = (const float*)d_in[5];
    const float* We2  = (const float*)d_in[6];
    const float* be2  = (const float*)d_in[7];
    const float* Wn1  = (const float*)d_in[8];
    const float* bn1  = (const float*)d_in[9];
    const float* Wn2  = (const float*)d_in[10];
    const float* bn2  = (const float*)d_in[11];
    float* out = (float*)d_out;

    const int TB = 256;
    const int nodeBlocks = (NN + TB - 1) / TB;
    const int edgeBlocks = (NE + TB - 1) / TB;
    const int cvtBlocks  = (2 * NE + TB - 1) / TB;

    k_detect<<<1, 1>>>((const unsigned*)eidx);
    k_convert<<<cvtBlocks, TB>>>(eidx);
    k_init<<<nodeBlocks, TB>>>(x, W_in, b_in, We1, be1, Wn1);
    for (int it = 0; it < 3; it++) {
        k_edge<<<edgeBlocks, TB>>>(We2, be2);
        k_node<<<nodeBlocks, TB>>>(We1, be1, Wn1, bn1, Wn2, bn2);
    }
    k_out<<<edgeBlocks, TB>>>(We2, be2, out);
}